// round 2
// baseline (speedup 1.0000x reference)
#include <cuda_runtime.h>

#define BN   2048
#define DD   32
#define NIDS 8192
#define KNN  30
#define TI   16
#define NTHR 256
#define JH   1024   // j-range per CTA (BN / 2 halves)

// Scratch (no allocations allowed)
__device__ float g_sq[BN];
__device__ float g_zT[DD * BN];
__device__ float g_pden[2 * BN];
__device__ float g_pnum[2 * BN];
__device__ float g_pany[2 * BN];

__device__ __forceinline__ unsigned long long pack2(float x, float y) {
    unsigned long long r;
    asm("mov.b64 %0, {%1, %2};" : "=l"(r) : "f"(x), "f"(y));
    return r;
}
__device__ __forceinline__ void unpack2(unsigned long long v, float &x, float &y) {
    asm("mov.b64 {%0, %1}, %2;" : "=f"(x), "=f"(y) : "l"(v));
}
__device__ __forceinline__ unsigned long long fma2(unsigned long long a,
                                                   unsigned long long b,
                                                   unsigned long long c) {
    unsigned long long d;
    asm("fma.rn.f32x2 %0, %1, %2, %3;" : "=l"(d) : "l"(a), "l"(b), "l"(c));
    return d;
}

// Kernel 1: squared norms + transpose z -> zT[k][j]. 64 CTAs x 256 thr.
// Warp w handles float4 chunk w of each row; lanes cover 32 consecutive j.
__global__ void __launch_bounds__(NTHR) prep_kernel(const float* __restrict__ z) {
    __shared__ float s_part[8][33];
    const int t = threadIdx.x;
    const int lane = t & 31;
    const int w = t >> 5;
    const int j = blockIdx.x * 32 + lane;

    float4 v = ((const float4*)z)[j * 8 + w];
    float p = v.x * v.x + v.y * v.y + v.z * v.z + v.w * v.w;

    // coalesced stores: fixed (w,r), consecutive lanes -> consecutive j
    g_zT[(w * 4 + 0) * BN + j] = v.x;
    g_zT[(w * 4 + 1) * BN + j] = v.y;
    g_zT[(w * 4 + 2) * BN + j] = v.z;
    g_zT[(w * 4 + 3) * BN + j] = v.w;

    s_part[w][lane] = p;
    __syncthreads();
    if (w == 0) {
        float s = 0.f;
#pragma unroll
        for (int r = 0; r < 8; r++) s += s_part[r][lane];
        g_sq[j] = s;
    }
}

// Kernel 2: grid (BN/TI, 2). CTA (x,y): rows [x*TI, x*TI+TI), j in [y*JH, y*JH+JH).
__global__ void __launch_bounds__(NTHR)
main_kernel(const float* __restrict__ z,
            const int* __restrict__ knn,
            const int* __restrict__ sid) {
    // z_i tile: [k][TI floats] packed as 4 x ulonglong2 per k -> 2KB
    __shared__ ulonglong2 s_zi[DD][4];
    // membership bitsets: 16 rows x 8192 bits = 16KB
    __shared__ unsigned s_bits[TI * 256];
    __shared__ float s_sqi[TI];
    __shared__ float s_rd[NTHR / 32][TI];
    __shared__ float s_rn[NTHR / 32][TI];
    __shared__ unsigned s_ra[NTHR / 32];

    const int t = threadIdx.x;
    const int row0 = blockIdx.x * TI;
    const int j0 = blockIdx.y * JH;

    // zero bitsets
#pragma unroll
    for (int w = t; w < TI * 256; w += NTHR) s_bits[w] = 0u;

    // load z_i tile: 512 floats; coalesced read of z, scatter into smem
#pragma unroll
    for (int idx = t; idx < TI * DD; idx += NTHR) {
        int k = idx & 31;
        int r = idx >> 5;
        ((float*)s_zi)[k * TI + r] = z[(row0 + r) * DD + k];
    }
    if (t < TI) s_sqi[t] = g_sq[row0 + t];
    __syncthreads();

    // populate bitsets: TI*KNN = 480 entries
    for (int idx = t; idx < TI * KNN; idx += NTHR) {
        int r = idx / KNN;
        int kk = idx - r * KNN;
        int srow = sid[row0 + r];
        int id = knn[srow * KNN + kk];
        atomicOr(&s_bits[r * 256 + (id >> 5)], 1u << (id & 31));
    }
    __syncthreads();

    float den[TI], num[TI];
#pragma unroll
    for (int r = 0; r < TI; r++) { den[r] = 0.f; num[r] = 0.f; }
    unsigned anyM = 0u;

#pragma unroll 1
    for (int j = j0 + t; j < j0 + JH; j += NTHR) {
        int sj = sid[j];
        unsigned wi = ((unsigned)sj) >> 5;
        unsigned bi = 1u << (sj & 31);
        unsigned m = 0u;
#pragma unroll
        for (int r = 0; r < TI; r++)
            m |= ((s_bits[r * 256 + wi] & bi) ? 1u : 0u) << r;

        float sqj = g_sq[j];

        unsigned long long a0 = 0ull, a1 = 0ull, a2 = 0ull, a3 = 0ull;
        unsigned long long a4 = 0ull, a5 = 0ull, a6 = 0ull, a7 = 0ull;
#pragma unroll
        for (int k = 0; k < DD; k++) {
            float vj = g_zT[k * BN + j];
            unsigned long long v2 = pack2(vj, vj);
            ulonglong2 p0 = s_zi[k][0];
            ulonglong2 p1 = s_zi[k][1];
            ulonglong2 p2 = s_zi[k][2];
            ulonglong2 p3 = s_zi[k][3];
            a0 = fma2(p0.x, v2, a0);
            a1 = fma2(p0.y, v2, a1);
            a2 = fma2(p1.x, v2, a2);
            a3 = fma2(p1.y, v2, a3);
            a4 = fma2(p2.x, v2, a4);
            a5 = fma2(p2.y, v2, a5);
            a6 = fma2(p3.x, v2, a6);
            a7 = fma2(p3.y, v2, a7);
        }
        float dot[TI];
        unpack2(a0, dot[0], dot[1]);
        unpack2(a1, dot[2], dot[3]);
        unpack2(a2, dot[4], dot[5]);
        unpack2(a3, dot[6], dot[7]);
        unpack2(a4, dot[8], dot[9]);
        unpack2(a5, dot[10], dot[11]);
        unpack2(a6, dot[12], dot[13]);
        unpack2(a7, dot[14], dot[15]);

        int dr = j - row0;  // diagonal hits row r == dr (if in range)
#pragma unroll
        for (int r = 0; r < TI; r++) {
            float d2 = fmaf(-2.f, dot[r], s_sqi[r] + sqj);
            d2 = fmaxf(d2, 0.f);
            float dist = d2 * rsqrtf(d2);   // MUFU.RSQ (fast), NOT __frsqrt_rn
            dist = (d2 > 0.f) ? dist : 0.f;
            float e = __expf(-dist);
            bool diag = (r == dr);
            e = diag ? 0.f : e;
            den[r] += e;
            bool msk = (((m >> r) & 1u) != 0u) && !diag;
            num[r] += msk ? e : 0.f;
            anyM |= (msk ? 1u : 0u) << r;
        }
    }

    // intra-warp reduce
#pragma unroll
    for (int r = 0; r < TI; r++) {
#pragma unroll
        for (int off = 16; off > 0; off >>= 1) {
            den[r] += __shfl_xor_sync(0xffffffffu, den[r], off);
            num[r] += __shfl_xor_sync(0xffffffffu, num[r], off);
        }
    }
    anyM = __reduce_or_sync(0xffffffffu, anyM);

    int warp = t >> 5, lane = t & 31;
    if (lane == 0) {
#pragma unroll
        for (int r = 0; r < TI; r++) {
            s_rd[warp][r] = den[r];
            s_rn[warp][r] = num[r];
        }
        s_ra[warp] = anyM;
    }
    __syncthreads();

    if (t < TI) {
        float dsum = 0.f, nsum = 0.f;
        unsigned a = 0u;
#pragma unroll
        for (int w = 0; w < NTHR / 32; w++) {
            dsum += s_rd[w][t];
            nsum += s_rn[w][t];
            a |= s_ra[w];
        }
        int o = blockIdx.y * BN + row0 + t;
        g_pden[o] = dsum;
        g_pnum[o] = nsum;
        g_pany[o] = (((a >> t) & 1u) != 0u) ? 1.f : 0.f;
    }
}

// Kernel 3: combine halves, per-row loss, deterministic reduction to scalar.
__global__ void __launch_bounds__(256) finish_kernel(float* __restrict__ out) {
    __shared__ float sl[8], sv[8];
    int t = threadIdx.x;
    float tot = 0.f, cnt = 0.f;
    for (int i = t; i < BN; i += 256) {
        float den = g_pden[i] + g_pden[BN + i];
        float num = g_pnum[i] + g_pnum[BN + i];
        float any = g_pany[i] + g_pany[BN + i];
        bool valid = any > 0.f;
        float s = num / den;
        float loss = -__logf(s + 1e-8f);
        tot += valid ? loss : 0.f;
        cnt += valid ? 1.f : 0.f;
    }
#pragma unroll
    for (int off = 16; off > 0; off >>= 1) {
        tot += __shfl_xor_sync(0xffffffffu, tot, off);
        cnt += __shfl_xor_sync(0xffffffffu, cnt, off);
    }
    if ((t & 31) == 0) { sl[t >> 5] = tot; sv[t >> 5] = cnt; }
    __syncthreads();
    if (t == 0) {
        float T = 0.f, C = 0.f;
#pragma unroll
        for (int w = 0; w < 8; w++) { T += sl[w]; C += sv[w]; }
        out[0] = (C > 0.f) ? (T / C) : 0.f;
    }
}

extern "C" void kernel_launch(void* const* d_in, const int* in_sizes, int n_in,
                              void* d_out, int out_size) {
    const float* z   = (const float*)d_in[0];
    const int*   knn = (const int*)d_in[1];
    const int*   sid = (const int*)d_in[2];
    (void)in_sizes; (void)n_in; (void)out_size;

    prep_kernel<<<BN / 32, NTHR>>>(z);
    main_kernel<<<dim3(BN / TI, 2, 1), NTHR>>>(z, knn, sid);
    finish_kernel<<<1, 256>>>((float*)d_out);
}

// round 3
// speedup vs baseline: 2.5576x; 2.5576x over previous
#include <cuda_runtime.h>

#define BN    2048
#define DD    32
#define NIDS  8192
#define KNN   30
#define TI    8
#define NTHR  256
#define YSPL  2
#define JH    (BN / YSPL)
#define NCTAS ((BN / TI) * YSPL)

// Scratch (no allocations allowed)
__device__ float g_sq[BN];
__device__ float g_zT[DD * BN];
__device__ float g_pden[YSPL * BN];
__device__ float g_pnum[YSPL * BN];
__device__ float g_pany[YSPL * BN];
__device__ unsigned g_cnt = 0;

__device__ __forceinline__ unsigned long long pack2(float x, float y) {
    unsigned long long r;
    asm("mov.b64 %0, {%1, %2};" : "=l"(r) : "f"(x), "f"(y));
    return r;
}
__device__ __forceinline__ void unpack2(unsigned long long v, float &x, float &y) {
    asm("mov.b64 {%0, %1}, %2;" : "=f"(x), "=f"(y) : "l"(v));
}
__device__ __forceinline__ unsigned long long fma2(unsigned long long a,
                                                   unsigned long long b,
                                                   unsigned long long c) {
    unsigned long long d;
    asm("fma.rn.f32x2 %0, %1, %2, %3;" : "=l"(d) : "l"(a), "l"(b), "l"(c));
    return d;
}

// Kernel 1: squared norms + transpose z -> zT[k][j]. 64 CTAs x 256 thr.
__global__ void __launch_bounds__(NTHR) prep_kernel(const float* __restrict__ z) {
    __shared__ float s_part[8][33];
    const int t = threadIdx.x;
    const int lane = t & 31;
    const int w = t >> 5;
    const int j = blockIdx.x * 32 + lane;

    float4 v = ((const float4*)z)[j * 8 + w];
    float p = v.x * v.x + v.y * v.y + v.z * v.z + v.w * v.w;

    g_zT[(w * 4 + 0) * BN + j] = v.x;
    g_zT[(w * 4 + 1) * BN + j] = v.y;
    g_zT[(w * 4 + 2) * BN + j] = v.z;
    g_zT[(w * 4 + 3) * BN + j] = v.w;

    s_part[w][lane] = p;
    __syncthreads();
    if (w == 0) {
        float s = 0.f;
#pragma unroll
        for (int r = 0; r < 8; r++) s += s_part[r][lane];
        g_sq[j] = s;
    }
}

// Kernel 2: grid (BN/TI, YSPL). CTA (x,y): rows [x*TI, x*TI+TI), j in [y*JH, (y+1)*JH).
// Last finishing CTA performs the final scalar reduction (threadfence pattern).
__global__ void __launch_bounds__(NTHR)
main_kernel(const float* __restrict__ z,
            const int* __restrict__ knn,
            const int* __restrict__ sid,
            float* __restrict__ out) {
    // z_i tile: floats at index k*TI + r, viewed as [k][2 x ulonglong2] -> 1KB
    __shared__ ulonglong2 s_zi[DD][2];
    // packed membership: word (id>>2), byte (id&3), bit r  -> 8KB
    __shared__ unsigned s_mb[NIDS / 4];
    __shared__ float s_sqi[TI];
    __shared__ float s_rd[NTHR / 32][TI];
    __shared__ float s_rn[NTHR / 32][TI];
    __shared__ unsigned s_ra[NTHR / 32];
    __shared__ bool s_last;

    const int t = threadIdx.x;
    const int row0 = blockIdx.x * TI;
    const int j0 = blockIdx.y * JH;

#pragma unroll
    for (int w = t; w < NIDS / 4; w += NTHR) s_mb[w] = 0u;

    // load z_i tile: 256 floats
    {
        int k = t & 31;
        int r = t >> 5;
        ((float*)s_zi)[k * TI + r] = z[(row0 + r) * DD + k];
    }
    if (t < TI) s_sqi[t] = g_sq[row0 + t];
    __syncthreads();

    // populate packed mask: TI*KNN = 240 entries
    if (t < TI * KNN) {
        int r = t / KNN;
        int kk = t - r * KNN;
        int srow = sid[row0 + r];
        int id = knn[srow * KNN + kk];
        atomicOr(&s_mb[id >> 2], (1u << r) << ((id & 3) * 8));
    }
    __syncthreads();

    float den[TI], num[TI];
#pragma unroll
    for (int r = 0; r < TI; r++) { den[r] = 0.f; num[r] = 0.f; }
    unsigned anyM = 0u;

#pragma unroll 1
    for (int j = j0 + t; j < j0 + JH; j += NTHR) {
        int sj = sid[j];
        unsigned m = (s_mb[sj >> 2] >> ((sj & 3) * 8)) & 0xffu;

        float sqj = g_sq[j];

        unsigned long long a0 = 0ull, a1 = 0ull, a2 = 0ull, a3 = 0ull;
#pragma unroll
        for (int k = 0; k < DD; k++) {
            float vj = g_zT[k * BN + j];
            unsigned long long v2 = pack2(vj, vj);
            ulonglong2 p0 = s_zi[k][0];
            ulonglong2 p1 = s_zi[k][1];
            a0 = fma2(p0.x, v2, a0);
            a1 = fma2(p0.y, v2, a1);
            a2 = fma2(p1.x, v2, a2);
            a3 = fma2(p1.y, v2, a3);
        }
        float dot[TI];
        unpack2(a0, dot[0], dot[1]);
        unpack2(a1, dot[2], dot[3]);
        unpack2(a2, dot[4], dot[5]);
        unpack2(a3, dot[6], dot[7]);

        int dr = j - row0;
#pragma unroll
        for (int r = 0; r < TI; r++) {
            float d2 = fmaf(-2.f, dot[r], s_sqi[r] + sqj);
            d2 = fmaxf(d2, 1e-20f);          // rsqrt-safe; ~exp(0) when d2~0
            float dist = d2 * rsqrtf(d2);    // MUFU.RSQ
            float e = __expf(-dist);         // FMUL + MUFU.EX2
            bool diag = (r == dr);
            e = diag ? 0.f : e;
            den[r] += e;
            bool msk = ((m >> r) & 1u) != 0u;
            msk = msk && !diag;
            num[r] += msk ? e : 0.f;
            anyM |= (msk ? 1u : 0u) << r;
        }
    }

    // intra-warp reduce
#pragma unroll
    for (int r = 0; r < TI; r++) {
#pragma unroll
        for (int off = 16; off > 0; off >>= 1) {
            den[r] += __shfl_xor_sync(0xffffffffu, den[r], off);
            num[r] += __shfl_xor_sync(0xffffffffu, num[r], off);
        }
    }
    anyM = __reduce_or_sync(0xffffffffu, anyM);

    int warp = t >> 5, lane = t & 31;
    if (lane == 0) {
#pragma unroll
        for (int r = 0; r < TI; r++) {
            s_rd[warp][r] = den[r];
            s_rn[warp][r] = num[r];
        }
        s_ra[warp] = anyM;
    }
    __syncthreads();

    if (t < TI) {
        float dsum = 0.f, nsum = 0.f;
        unsigned a = 0u;
#pragma unroll
        for (int w = 0; w < NTHR / 32; w++) {
            dsum += s_rd[w][t];
            nsum += s_rn[w][t];
            a |= s_ra[w];
        }
        int o = blockIdx.y * BN + row0 + t;
        g_pden[o] = dsum;
        g_pnum[o] = nsum;
        g_pany[o] = (((a >> t) & 1u) != 0u) ? 1.f : 0.f;
    }

    // ---- last-block final reduction (deterministic) ----
    __threadfence();
    if (t == 0) {
        unsigned old = atomicAdd(&g_cnt, 1u);
        s_last = (old == NCTAS - 1);
    }
    __syncthreads();
    if (!s_last) return;

    __threadfence();  // acquire: make all partials visible
    float tot = 0.f, cnt = 0.f;
#pragma unroll
    for (int i = t; i < BN; i += NTHR) {
        float dv = __ldcg(&g_pden[i]) + __ldcg(&g_pden[BN + i]);
        float nv = __ldcg(&g_pnum[i]) + __ldcg(&g_pnum[BN + i]);
        float av = __ldcg(&g_pany[i]) + __ldcg(&g_pany[BN + i]);
        bool valid = av > 0.f;
        float s = nv / dv;
        float loss = -__logf(s + 1e-8f);
        tot += valid ? loss : 0.f;
        cnt += valid ? 1.f : 0.f;
    }
#pragma unroll
    for (int off = 16; off > 0; off >>= 1) {
        tot += __shfl_xor_sync(0xffffffffu, tot, off);
        cnt += __shfl_xor_sync(0xffffffffu, cnt, off);
    }
    if (lane == 0) { s_rd[warp][0] = tot; s_rn[warp][0] = cnt; }
    __syncthreads();
    if (t == 0) {
        float T = 0.f, C = 0.f;
#pragma unroll
        for (int w = 0; w < NTHR / 32; w++) { T += s_rd[w][0]; C += s_rn[w][0]; }
        out[0] = (C > 0.f) ? (T / C) : 0.f;
        g_cnt = 0;  // reset for next graph replay
    }
}

extern "C" void kernel_launch(void* const* d_in, const int* in_sizes, int n_in,
                              void* d_out, int out_size) {
    const float* z   = (const float*)d_in[0];
    const int*   knn = (const int*)d_in[1];
    const int*   sid = (const int*)d_in[2];
    (void)in_sizes; (void)n_in; (void)out_size;

    prep_kernel<<<BN / 32, NTHR>>>(z);
    main_kernel<<<dim3(BN / TI, YSPL, 1), NTHR>>>(z, knn, sid, (float*)d_out);
}

// round 4
// speedup vs baseline: 3.6897x; 1.4426x over previous
#include <cuda_runtime.h>

#define BN    2048
#define DD    32
#define NIDS  8192
#define KNN   30
#define TI    16
#define NTHR  256
#define YSPL  4
#define JH    (BN / YSPL)          // 512
#define NCTAS ((BN / TI) * YSPL)   // 512

// Scratch (no allocations allowed)
__device__ float g_sq[BN];
__device__ float g_zT[DD * BN];
__device__ float g_pden[YSPL * BN];
__device__ float g_pnum[YSPL * BN];
__device__ float g_pany[YSPL * BN];
__device__ unsigned g_cnt = 0;

__device__ __forceinline__ unsigned long long pack2(float x, float y) {
    unsigned long long r;
    asm("mov.b64 %0, {%1, %2};" : "=l"(r) : "f"(x), "f"(y));
    return r;
}
__device__ __forceinline__ void unpack2(unsigned long long v, float &x, float &y) {
    asm("mov.b64 {%0, %1}, %2;" : "=f"(x), "=f"(y) : "l"(v));
}
__device__ __forceinline__ unsigned long long fma2(unsigned long long a,
                                                   unsigned long long b,
                                                   unsigned long long c) {
    unsigned long long d;
    asm("fma.rn.f32x2 %0, %1, %2, %3;" : "=l"(d) : "l"(a), "l"(b), "l"(c));
    return d;
}
__device__ __forceinline__ float fsqrt_approx(float x) {
    float r;
    asm("sqrt.approx.f32 %0, %1;" : "=f"(r) : "f"(x));
    return r;
}

// Kernel 1: coalesced read -> smem transpose -> sector-aligned zT write + norms.
// grid 256 CTAs x 256 thr; CTA b handles rows [b*8, b*8+8).
__global__ void __launch_bounds__(NTHR) prep_kernel(const float* __restrict__ z) {
    __shared__ float sf[8 * 33];
    const int t = threadIdx.x;
    const int idx = blockIdx.x * NTHR + t;   // global element
    const float v = __ldg(&z[idx]);          // fully coalesced

    // norm: one warp == one row (32 k's)
    float s = v * v;
#pragma unroll
    for (int off = 16; off > 0; off >>= 1)
        s += __shfl_xor_sync(0xffffffffu, s, off);
    if ((t & 31) == 0) g_sq[idx >> 5] = s;

    sf[(t >> 5) * 33 + (t & 31)] = v;        // row-padded tile
    __syncthreads();

    const int k2 = t >> 3;                   // 0..31
    const int jo = t & 7;                    // 0..7
    g_zT[k2 * BN + blockIdx.x * 8 + jo] = sf[jo * 33 + k2];  // 32B segments
}

// Kernel 2: grid (BN/TI, YSPL). CTA (x,y): rows [x*TI, x*TI+TI), j in [y*JH, (y+1)*JH).
// Each thread owns exactly 2 consecutive j (single pass -> nothing to hoist).
__global__ void __launch_bounds__(NTHR, 2)
main_kernel(const float* __restrict__ z,
            const int* __restrict__ knn,
            const int* __restrict__ sid,
            float* __restrict__ out) {
    // z_i tile as row-pairs: u64 index k*8+p holds (zi[2p][k], zi[2p+1][k]) -> 2KB
    __shared__ unsigned long long s_zi[DD * (TI / 2)];
    // packed membership: 16 bits per id, 2 ids per word -> 16KB
    __shared__ unsigned s_mb[NIDS / 2];
    __shared__ float s_sqi[TI];
    __shared__ float s_rd[NTHR / 32][TI];
    __shared__ float s_rn[NTHR / 32][TI];
    __shared__ unsigned s_ra[NTHR / 32];
    __shared__ bool s_last;

    const int t = threadIdx.x;
    const int row0 = blockIdx.x * TI;
    const int j0 = blockIdx.y * JH;

#pragma unroll
    for (int w = t; w < NIDS / 2; w += NTHR) s_mb[w] = 0u;

    // fill z_i tile: 512 floats; float layout sf[k*TI + r]
    {
        float* sf = (float*)s_zi;
#pragma unroll
        for (int idx = t; idx < TI * DD; idx += NTHR) {
            int k = idx & 31;
            int r = idx >> 5;
            sf[k * TI + r] = z[(row0 + r) * DD + k];
        }
    }
    if (t < TI) s_sqi[t] = g_sq[row0 + t];
    __syncthreads();

    // populate packed mask: TI*KNN = 480 entries
#pragma unroll
    for (int idx = t; idx < TI * KNN; idx += NTHR) {
        int r = idx / KNN;
        int kk = idx - r * KNN;
        int srow = sid[row0 + r];
        int id = knn[srow * KNN + kk];
        atomicOr(&s_mb[id >> 1], (1u << r) << ((id & 1) * 16));
    }
    __syncthreads();

    // ---- single pass: this thread owns j and j+1 ----
    const int j = j0 + t * 2;
    const int sj0 = sid[j];
    const int sj1 = sid[j + 1];
    const unsigned m0 = (s_mb[sj0 >> 1] >> ((sj0 & 1) * 16)) & 0xffffu;
    const unsigned m1 = (s_mb[sj1 >> 1] >> ((sj1 & 1) * 16)) & 0xffffu;
    const float sqj0 = g_sq[j];
    const float sqj1 = g_sq[j + 1];

    unsigned long long acc0[TI / 2], acc1[TI / 2];
#pragma unroll
    for (int p = 0; p < TI / 2; p++) { acc0[p] = 0ull; acc1[p] = 0ull; }

    const float2* zT2 = (const float2*)g_zT;
#pragma unroll 4
    for (int k = 0; k < DD; k++) {
        float2 vj = zT2[(k * BN + j) >> 1];       // coalesced: 2 j's per load
        unsigned long long v0 = pack2(vj.x, vj.x);
        unsigned long long v1 = pack2(vj.y, vj.y);
#pragma unroll
        for (int p = 0; p < TI / 2; p++) {
            unsigned long long zp = s_zi[k * (TI / 2) + p];
            acc0[p] = fma2(zp, v0, acc0[p]);
            acc1[p] = fma2(zp, v1, acc1[p]);
        }
    }

    float den[TI], num[TI];
    unsigned anyM = 0u;
    {
        float dot0[TI], dot1[TI];
#pragma unroll
        for (int p = 0; p < TI / 2; p++) {
            unpack2(acc0[p], dot0[2 * p], dot0[2 * p + 1]);
            unpack2(acc1[p], dot1[2 * p], dot1[2 * p + 1]);
        }
#pragma unroll
        for (int r = 0; r < TI; r++) {
            // j
            float d2 = fmaf(-2.f, dot0[r], s_sqi[r] + sqj0);
            d2 = fmaxf(d2, 1e-20f);
            float e0 = __expf(-fsqrt_approx(d2));
            bool diag0 = (j == row0 + r);
            e0 = diag0 ? 0.f : e0;
            bool k0 = (((m0 >> r) & 1u) != 0u) && !diag0;
            // j+1
            float d2b = fmaf(-2.f, dot1[r], s_sqi[r] + sqj1);
            d2b = fmaxf(d2b, 1e-20f);
            float e1 = __expf(-fsqrt_approx(d2b));
            bool diag1 = (j + 1 == row0 + r);
            e1 = diag1 ? 0.f : e1;
            bool k1 = (((m1 >> r) & 1u) != 0u) && !diag1;

            den[r] = e0 + e1;
            num[r] = (k0 ? e0 : 0.f) + (k1 ? e1 : 0.f);
            anyM |= ((k0 || k1) ? 1u : 0u) << r;
        }
    }

    // intra-warp reduce
#pragma unroll
    for (int r = 0; r < TI; r++) {
#pragma unroll
        for (int off = 16; off > 0; off >>= 1) {
            den[r] += __shfl_xor_sync(0xffffffffu, den[r], off);
            num[r] += __shfl_xor_sync(0xffffffffu, num[r], off);
        }
    }
    anyM = __reduce_or_sync(0xffffffffu, anyM);

    const int warp = t >> 5, lane = t & 31;
    if (lane == 0) {
#pragma unroll
        for (int r = 0; r < TI; r++) {
            s_rd[warp][r] = den[r];
            s_rn[warp][r] = num[r];
        }
        s_ra[warp] = anyM;
    }
    __syncthreads();

    if (t < TI) {
        float dsum = 0.f, nsum = 0.f;
        unsigned a = 0u;
#pragma unroll
        for (int w = 0; w < NTHR / 32; w++) {
            dsum += s_rd[w][t];
            nsum += s_rn[w][t];
            a |= s_ra[w];
        }
        int o = blockIdx.y * BN + row0 + t;
        g_pden[o] = dsum;
        g_pnum[o] = nsum;
        g_pany[o] = (((a >> t) & 1u) != 0u) ? 1.f : 0.f;
    }

    // ---- last-block final reduction (deterministic) ----
    __threadfence();
    if (t == 0) {
        unsigned old = atomicAdd(&g_cnt, 1u);
        s_last = (old == NCTAS - 1);
    }
    __syncthreads();
    if (!s_last) return;

    __threadfence();
    float tot = 0.f, cnt = 0.f;
#pragma unroll
    for (int i = t; i < BN; i += NTHR) {
        float dv = 0.f, nv = 0.f, av = 0.f;
#pragma unroll
        for (int y = 0; y < YSPL; y++) {
            dv += __ldcg(&g_pden[y * BN + i]);
            nv += __ldcg(&g_pnum[y * BN + i]);
            av += __ldcg(&g_pany[y * BN + i]);
        }
        bool valid = av > 0.f;
        float sr = nv / dv;
        float loss = -__logf(sr + 1e-8f);
        tot += valid ? loss : 0.f;
        cnt += valid ? 1.f : 0.f;
    }
#pragma unroll
    for (int off = 16; off > 0; off >>= 1) {
        tot += __shfl_xor_sync(0xffffffffu, tot, off);
        cnt += __shfl_xor_sync(0xffffffffu, cnt, off);
    }
    if (lane == 0) { s_rd[warp][0] = tot; s_rn[warp][0] = cnt; }
    __syncthreads();
    if (t == 0) {
        float T = 0.f, C = 0.f;
#pragma unroll
        for (int w = 0; w < NTHR / 32; w++) { T += s_rd[w][0]; C += s_rn[w][0]; }
        out[0] = (C > 0.f) ? (T / C) : 0.f;
        g_cnt = 0;  // reset for next graph replay
    }
}

extern "C" void kernel_launch(void* const* d_in, const int* in_sizes, int n_in,
                              void* d_out, int out_size) {
    const float* z   = (const float*)d_in[0];
    const int*   knn = (const int*)d_in[1];
    const int*   sid = (const int*)d_in[2];
    (void)in_sizes; (void)n_in; (void)out_size;

    prep_kernel<<<(BN * DD) / NTHR, NTHR>>>(z);
    main_kernel<<<dim3(BN / TI, YSPL, 1), NTHR>>>(z, knn, sid, (float*)d_out);
}

// round 5
// speedup vs baseline: 4.0243x; 1.0907x over previous
#include <cuda_runtime.h>

#define BN    2048
#define DD    32
#define NIDS  8192
#define KNN   30
#define TI    8
#define JPT   4
#define NTHR  256
#define JH    (NTHR * JPT)         // 1024
#define YSPL  (BN / JH)            // 2
#define NCTAS ((BN / TI) * YSPL)   // 512

// Scratch (no allocations allowed)
__device__ float g_sq[BN];
__device__ float g_zT[DD * BN];
__device__ float g_pden[YSPL * BN];
__device__ float g_pnum[YSPL * BN];
__device__ float g_pany[YSPL * BN];
__device__ unsigned g_cnt = 0;

__device__ __forceinline__ unsigned long long pack2(float x, float y) {
    unsigned long long r;
    asm("mov.b64 %0, {%1, %2};" : "=l"(r) : "f"(x), "f"(y));
    return r;
}
__device__ __forceinline__ void unpack2(unsigned long long v, float &x, float &y) {
    asm("mov.b64 {%0, %1}, %2;" : "=f"(x), "=f"(y) : "l"(v));
}
__device__ __forceinline__ unsigned long long fma2(unsigned long long a,
                                                   unsigned long long b,
                                                   unsigned long long c) {
    unsigned long long d;
    asm("fma.rn.f32x2 %0, %1, %2, %3;" : "=l"(d) : "l"(a), "l"(b), "l"(c));
    return d;
}
__device__ __forceinline__ float fsqrt_approx(float x) {
    float r;
    asm("sqrt.approx.f32 %0, %1;" : "=f"(r) : "f"(x));
    return r;
}

// Kernel 1: coalesced read -> smem transpose -> zT write + norms.
__global__ void __launch_bounds__(NTHR) prep_kernel(const float* __restrict__ z) {
    __shared__ float sf[8 * 33];
    const int t = threadIdx.x;
    const int idx = blockIdx.x * NTHR + t;
    const float v = __ldg(&z[idx]);

    float s = v * v;
#pragma unroll
    for (int off = 16; off > 0; off >>= 1)
        s += __shfl_xor_sync(0xffffffffu, s, off);
    if ((t & 31) == 0) g_sq[idx >> 5] = s;

    sf[(t >> 5) * 33 + (t & 31)] = v;
    __syncthreads();

    const int k2 = t >> 3;
    const int jo = t & 7;
    g_zT[k2 * BN + blockIdx.x * 8 + jo] = sf[jo * 33 + k2];
}

// Kernel 2: grid (BN/TI, YSPL). CTA (x,y): rows [x*TI, +TI), j in [y*JH, +JH).
// Each thread owns exactly JPT=4 consecutive j's. Single pass.
__global__ void __launch_bounds__(NTHR, 3)
main_kernel(const float* __restrict__ z,
            const int* __restrict__ knn,
            const int* __restrict__ sid,
            float* __restrict__ out) {
    // z_i row-pairs: u64 index k*4+p = (zi[2p][k], zi[2p+1][k]) -> 1KB
    __shared__ unsigned long long s_zi[DD * (TI / 2)];
    // byte-packed membership: byte (id&3) of word (id>>2), bit r -> 8KB
    __shared__ unsigned s_mb[NIDS / 4];
    __shared__ float s_sqi[TI];
    __shared__ float s_rd[NTHR / 32][TI];
    __shared__ float s_rn[NTHR / 32][TI];
    __shared__ unsigned s_ra[NTHR / 32];
    __shared__ bool s_last;

    const int t = threadIdx.x;
    const int row0 = blockIdx.x * TI;
    const int j0 = blockIdx.y * JH;

#pragma unroll
    for (int w = t; w < NIDS / 4; w += NTHR) s_mb[w] = 0u;

    // fill z_i tile (256 floats): sf[k*TI + r]
    {
        float* sf = (float*)s_zi;
        int k = t & 31;
        int r = t >> 5;
        sf[k * TI + r] = z[(row0 + r) * DD + k];
    }
    if (t < TI) s_sqi[t] = g_sq[row0 + t];
    __syncthreads();

    // populate packed mask: TI*KNN = 240 entries
    if (t < TI * KNN) {
        int r = t / KNN;
        int kk = t - r * KNN;
        int srow = sid[row0 + r];
        int id = knn[srow * KNN + kk];
        atomicOr(&s_mb[id >> 2], (1u << r) << ((id & 3) * 8));
    }
    __syncthreads();

    // ---- single pass: this thread owns j..j+3 ----
    const int j = j0 + t * JPT;
    const int4 sjv = ((const int4*)sid)[j >> 2];
    unsigned m[JPT];
    m[0] = (s_mb[sjv.x >> 2] >> ((sjv.x & 3) * 8)) & 0xffu;
    m[1] = (s_mb[sjv.y >> 2] >> ((sjv.y & 3) * 8)) & 0xffu;
    m[2] = (s_mb[sjv.z >> 2] >> ((sjv.z & 3) * 8)) & 0xffu;
    m[3] = (s_mb[sjv.w >> 2] >> ((sjv.w & 3) * 8)) & 0xffu;
    const float4 sqjv = ((const float4*)g_sq)[j >> 2];

    unsigned long long acc[TI / 2][JPT];
#pragma unroll
    for (int p = 0; p < TI / 2; p++)
#pragma unroll
        for (int q = 0; q < JPT; q++) acc[p][q] = 0ull;

    const float4* zT4 = (const float4*)g_zT;
#pragma unroll 4
    for (int k = 0; k < DD; k++) {
        float4 vj = zT4[(k * BN + j) >> 2];   // one LDG.128 = 4 j's
        unsigned long long v0 = pack2(vj.x, vj.x);
        unsigned long long v1 = pack2(vj.y, vj.y);
        unsigned long long v2 = pack2(vj.z, vj.z);
        unsigned long long v3 = pack2(vj.w, vj.w);
#pragma unroll
        for (int p = 0; p < TI / 2; p++) {
            unsigned long long zp = s_zi[k * (TI / 2) + p];
            acc[p][0] = fma2(zp, v0, acc[p][0]);
            acc[p][1] = fma2(zp, v1, acc[p][1]);
            acc[p][2] = fma2(zp, v2, acc[p][2]);
            acc[p][3] = fma2(zp, v3, acc[p][3]);
        }
    }

    float den[TI], num[TI];
    unsigned anyM = 0u;
    {
        float sqj[JPT] = {sqjv.x, sqjv.y, sqjv.z, sqjv.w};
#pragma unroll
        for (int p = 0; p < TI / 2; p++) {
#pragma unroll
            for (int rr = 0; rr < 2; rr++) {
                int r = 2 * p + rr;
                float base = s_sqi[r];
                float e[JPT];
                bool kk[JPT];
#pragma unroll
                for (int q = 0; q < JPT; q++) {
                    float d0, d1;
                    unpack2(acc[p][q], d0, d1);
                    float dot = rr ? d1 : d0;
                    float d2 = fmaf(-2.f, dot, base + sqj[q]);
                    d2 = fmaxf(d2, 1e-20f);
                    float ev = __expf(-fsqrt_approx(d2));
                    bool diag = (j + q == row0 + r);
                    ev = diag ? 0.f : ev;
                    e[q] = ev;
                    kk[q] = (((m[q] >> r) & 1u) != 0u) && !diag;
                }
                den[r] = (e[0] + e[1]) + (e[2] + e[3]);
                num[r] = ((kk[0] ? e[0] : 0.f) + (kk[1] ? e[1] : 0.f)) +
                         ((kk[2] ? e[2] : 0.f) + (kk[3] ? e[3] : 0.f));
                anyM |= ((kk[0] || kk[1] || kk[2] || kk[3]) ? 1u : 0u) << r;
            }
        }
    }

    // intra-warp reduce
#pragma unroll
    for (int r = 0; r < TI; r++) {
#pragma unroll
        for (int off = 16; off > 0; off >>= 1) {
            den[r] += __shfl_xor_sync(0xffffffffu, den[r], off);
            num[r] += __shfl_xor_sync(0xffffffffu, num[r], off);
        }
    }
    anyM = __reduce_or_sync(0xffffffffu, anyM);

    const int warp = t >> 5, lane = t & 31;
    if (lane == 0) {
#pragma unroll
        for (int r = 0; r < TI; r++) {
            s_rd[warp][r] = den[r];
            s_rn[warp][r] = num[r];
        }
        s_ra[warp] = anyM;
    }
    __syncthreads();

    if (t < TI) {
        float dsum = 0.f, nsum = 0.f;
        unsigned a = 0u;
#pragma unroll
        for (int w = 0; w < NTHR / 32; w++) {
            dsum += s_rd[w][t];
            nsum += s_rn[w][t];
            a |= s_ra[w];
        }
        int o = blockIdx.y * BN + row0 + t;
        g_pden[o] = dsum;
        g_pnum[o] = nsum;
        g_pany[o] = (((a >> t) & 1u) != 0u) ? 1.f : 0.f;
    }

    // ---- last-block final reduction (deterministic) ----
    __threadfence();
    if (t == 0) {
        unsigned old = atomicAdd(&g_cnt, 1u);
        s_last = (old == NCTAS - 1);
    }
    __syncthreads();
    if (!s_last) return;

    __threadfence();
    float tot = 0.f, cnt = 0.f;
#pragma unroll
    for (int i = t; i < BN; i += NTHR) {
        float dv = 0.f, nv = 0.f, av = 0.f;
#pragma unroll
        for (int y = 0; y < YSPL; y++) {
            dv += __ldcg(&g_pden[y * BN + i]);
            nv += __ldcg(&g_pnum[y * BN + i]);
            av += __ldcg(&g_pany[y * BN + i]);
        }
        bool valid = av > 0.f;
        float sr = nv / dv;
        float loss = -__logf(sr + 1e-8f);
        tot += valid ? loss : 0.f;
        cnt += valid ? 1.f : 0.f;
    }
#pragma unroll
    for (int off = 16; off > 0; off >>= 1) {
        tot += __shfl_xor_sync(0xffffffffu, tot, off);
        cnt += __shfl_xor_sync(0xffffffffu, cnt, off);
    }
    if (lane == 0) { s_rd[warp][0] = tot; s_rn[warp][0] = cnt; }
    __syncthreads();
    if (t == 0) {
        float T = 0.f, C = 0.f;
#pragma unroll
        for (int w = 0; w < NTHR / 32; w++) { T += s_rd[w][0]; C += s_rn[w][0]; }
        out[0] = (C > 0.f) ? (T / C) : 0.f;
        g_cnt = 0;  // reset for next graph replay
    }
}

extern "C" void kernel_launch(void* const* d_in, const int* in_sizes, int n_in,
                              void* d_out, int out_size) {
    const float* z   = (const float*)d_in[0];
    const int*   knn = (const int*)d_in[1];
    const int*   sid = (const int*)d_in[2];
    (void)in_sizes; (void)n_in; (void)out_size;

    prep_kernel<<<(BN * DD) / NTHR, NTHR>>>(z);
    main_kernel<<<dim3(BN / TI, YSPL, 1), NTHR>>>(z, knn, sid, (float*)d_out);
}